// round 10
// baseline (speedup 1.0000x reference)
#include <cuda_runtime.h>
#include <cstdint>

// Problem constants
#define CIN      32
#define COUT     64
#define OUT_DIM  1024
#define KP       4
#define DLEN     4096            // OUT_DIM * KP
#define BSZ      16
#define P_TILE   4               // patches per CTA
#define NTHREADS 256             // 8 warps, each owns 8 output channels
#define STAGES   12              // w pipeline depth (ring in smem)

#define XS_BYTES (BSZ * CIN * P_TILE * KP * 4)        // 32 KB
#define WS_STAGE_BYTES (COUT * P_TILE * KP * 4)       // 4 KB/stage
#define WS_BYTES (STAGES * WS_STAGE_BYTES)            // 48 KB
#define SMEM_BYTES (XS_BYTES + WS_BYTES)              // 80 KB -> 2 CTAs/SM

// Packed dual-FMA: only reachable via PTX fma.rn.f32x2.
__device__ __forceinline__ unsigned long long ffma2(unsigned long long a,
                                                    unsigned long long b,
                                                    unsigned long long c) {
    unsigned long long d;
    asm("fma.rn.f32x2 %0, %1, %2, %3;" : "=l"(d) : "l"(a), "l"(b), "l"(c));
    return d;
}

__device__ __forceinline__ void cp_async16(uint32_t dst_smem, const void* src) {
    asm volatile("cp.async.cg.shared.global [%0], [%1], 16;\n"
                 :: "r"(dst_smem), "l"(src));
}
__device__ __forceinline__ void cp_commit() {
    asm volatile("cp.async.commit_group;\n" ::);
}
template <int N>
__device__ __forceinline__ void cp_wait() {
    asm volatile("cp.async.wait_group %0;\n" :: "n"(N));
}

__global__ void __launch_bounds__(NTHREADS, 2)
lc1d_kernel(const float* __restrict__ x, const float* __restrict__ w,
            float* __restrict__ out) {
    extern __shared__ char smem[];

    const int tid  = threadIdx.x;
    const int lane = tid & 31;
    const int wid  = tid >> 5;           // 0..7
    const int p0   = blockIdx.x * P_TILE;   // also the float4 index of first patch

    const int p_l = lane & 3;            // patch within tile (one per thread)
    const int bg  = lane >> 2;           // 8 batch groups; thread covers b = bg, bg+8
    const int o0  = wid * 8;             // warp covers 8 output channels

    uint32_t smem_u32;
    asm("{ .reg .u64 t; cvta.to.shared.u64 t, %1; cvt.u32.u64 %0, t; }"
        : "=r"(smem_u32) : "l"(smem));
    const uint32_t xs_u32 = smem_u32;                 // x: [c][b][p] 16B chunks
    const uint32_t ws_u32 = smem_u32 + XS_BYTES;      // w ring: [stage][warp][8 rows x 64B]

    // ---- w staging map: warp stages its 8 o-rows (512B/warp/stage), 1 chunk/lane.
    const int rw = lane >> 2;            // row 0..7 (o0+rw)
    const int uw = lane & 3;             // 16B chunk within 64B row
    const float* wsrc0 = w + (size_t)(o0 + rw) * (CIN * DLEN) + p0 * KP + uw * 4;
    const uint32_t wdst0 = ws_u32 + wid * 512 + rw * 64 + uw * 16;

    // ---- Prologue ----
    // Group 0: all of x (8 x 16B per thread) + w stage 0.
    {
        const float4* xg = reinterpret_cast<const float4*>(x);
#pragma unroll
        for (int r = 0; r < 8; ++r) {
            int idx = tid + r * NTHREADS;          // 0..2047 chunk index = c*64 + b*4 + p
            int p = idx & 3;
            int b = (idx >> 2) & 15;
            int c = idx >> 6;
            cp_async16(xs_u32 + idx * 16, xg + (b * 32768 + c * 1024 + p0 + p));
        }
        cp_async16(wdst0, wsrc0);
        cp_commit();
    }
    // Groups 1..10: w stages 1..10
#pragma unroll
    for (int s = 1; s < STAGES - 1; ++s) {
        cp_async16(wdst0 + (s % STAGES) * WS_STAGE_BYTES, wsrc0 + s * DLEN);
        cp_commit();
    }

    cp_wait<STAGES - 2>();     // this thread's group 0 complete
    __syncthreads();           // -> all threads' group 0 complete: x + stage 0 visible

    unsigned long long acc[2][8];       // [b half][o] packed f32x2
#pragma unroll
    for (int i = 0; i < 2; ++i)
#pragma unroll
        for (int j = 0; j < 8; ++j) acc[i][j] = 0ULL;

    const uint32_t xaddr0 = xs_u32 + lane * 16;              // c*1024 + i*512 + lane*16
    const uint32_t waddr0 = ws_u32 + wid * 512 + p_l * 16;

#pragma unroll
    for (int c = 0; c < CIN; ++c) {
        if (c > 0) {
            cp_wait<STAGES - 2>();     // committed = 11+c, keep newest 10 -> group c+1 done
            __syncwarp();              // cross-lane visibility of warp's staged w
        }

        const uint32_t wst = waddr0 + (c % STAGES) * WS_STAGE_BYTES;
        const uint32_t xst = xaddr0 + c * 1024;

        // x: contiguous 512B per instruction (conflict-free): b = bg + 8i, p = p_l
        ulonglong2 xv[2];
#pragma unroll
        for (int i = 0; i < 2; ++i) {
            asm volatile("ld.shared.v2.u64 {%0, %1}, [%2];"
                         : "=l"(xv[i].x), "=l"(xv[i].y)
                         : "r"(xst + i * 512));
        }

        // w: warp's 8 staged rows (64B each), broadcast across the 8 b lane-groups
        ulonglong2 wv[8];
#pragma unroll
        for (int j = 0; j < 8; ++j) {
            asm volatile("ld.shared.v2.u64 {%0, %1}, [%2];"
                         : "=l"(wv[j].x), "=l"(wv[j].y)
                         : "r"(wst + j * 64));
        }

#pragma unroll
        for (int i = 0; i < 2; ++i)
#pragma unroll
            for (int j = 0; j < 8; ++j) {
                acc[i][j] = ffma2(wv[j].x, xv[i].x, acc[i][j]);   // k0,k1
                acc[i][j] = ffma2(wv[j].y, xv[i].y, acc[i][j]);   // k2,k3
            }

        // Refill stage c+11 into slot (c+11)%12. Commit EVERY iteration (possibly
        // empty) so wait_group<10> always means "stage c complete".
        if (c + (STAGES - 1) < CIN)
            cp_async16(wdst0 + ((c + STAGES - 1) % STAGES) * WS_STAGE_BYTES,
                       wsrc0 + (c + STAGES - 1) * DLEN);
        cp_commit();
    }

    // ---- Epilogue ----
    const float scale = 0.17677669529663687f;   // 1/sqrt(32)
    const int p = p0 + p_l;
#pragma unroll
    for (int i = 0; i < 2; ++i) {
        const int b = bg + i * 8;
#pragma unroll
        for (int j = 0; j < 8; ++j) {
            float2 v = *reinterpret_cast<float2*>(&acc[i][j]);
            out[b * (COUT * OUT_DIM) + (o0 + j) * OUT_DIM + p] =
                (v.x + v.y) * scale;
        }
    }
}

extern "C" void kernel_launch(void* const* d_in, const int* in_sizes, int n_in,
                              void* d_out, int out_size) {
    const float* x = (const float*)d_in[0];
    const float* w = (const float*)d_in[1];
    float* out = (float*)d_out;

    cudaFuncSetAttribute(lc1d_kernel, cudaFuncAttributeMaxDynamicSharedMemorySize,
                         SMEM_BYTES);

    lc1d_kernel<<<OUT_DIM / P_TILE, NTHREADS, SMEM_BYTES>>>(x, w, out);
}

// round 11
// speedup vs baseline: 1.1932x; 1.1932x over previous
#include <cuda_runtime.h>
#include <cstdint>

// Problem constants
#define CIN      32
#define COUT     64
#define OUT_DIM  1024
#define KP       4
#define DLEN     4096            // OUT_DIM * KP
#define BSZ      16
#define P_TILE   8               // patches per CTA
#define NTHREADS 512             // 16 warps: warp -> 4 o's
#define SMEM_BYTES (BSZ * CIN * P_TILE * KP * 4)   // 64 KB
#define NBUF     4               // w prefetch ring slots (distance 3 iters)

// Packed dual-FMA (PTX-only; ptxas won't auto-fuse).
__device__ __forceinline__ unsigned long long ffma2(unsigned long long a,
                                                    unsigned long long b,
                                                    unsigned long long c) {
    unsigned long long d;
    asm("fma.rn.f32x2 %0, %1, %2, %3;" : "=l"(d) : "l"(a), "l"(b), "l"(c));
    return d;
}

// Pinned-order 16B global load (volatile: ptxas preserves relative order of
// volatile asm, so prefetches cannot be sunk to their use sites).
__device__ __forceinline__ void ldg16_v(unsigned long long& lo, unsigned long long& hi,
                                        const float* p) {
    asm volatile("ld.global.nc.v2.u64 {%0, %1}, [%2];"
                 : "=l"(lo), "=l"(hi) : "l"(p));
}

__global__ void __launch_bounds__(NTHREADS, 1)
lc1d_kernel(const float* __restrict__ x, const float* __restrict__ w,
            float* __restrict__ out) {
    extern __shared__ float xs[];   // x: [b][c][32 floats] -> b*1024 + c*32 + d

    const int tid = threadIdx.x;
    const int p0  = blockIdx.x * P_TILE;

    // ---- Stage x slice: 16b x 32c x 32d floats = 4096 float4 ----
    {
        const float4* xg  = reinterpret_cast<const float4*>(x);
        float4*       xs4 = reinterpret_cast<float4*>(xs);
#pragma unroll
        for (int r = 0; r < 8; ++r) {
            int idx = tid + r * NTHREADS;      // 0..4095
            int q = idx & 7;
            int c = (idx >> 3) & 31;
            int b = idx >> 8;
            xs4[idx] = xg[b * 32768 + c * 1024 + p0 + q];
        }
    }

    // ---- Thread mapping (R2: LDG-minimal, w read once per SM) ----
    const int lane = tid & 31;
    const int p_l  = lane & 7;            // 8 contiguous patches
    const int b0   = (lane >> 3) * 4;     // 4 batch groups x Tb=4
    const int o0   = (tid >> 5) * 4;      // warp -> 4 output channels

    // Single w base; all (j, c) offsets are compile-time immediates (< 8 MB).
    const float* wbase = w + (size_t)o0 * (CIN * DLEN) + (p0 + p_l) * KP;
    const float* xsb   = xs + b0 * 1024 + p_l * 4;

    // ---- Preload ring slots 0..2 (w[0..2]) — overlaps x staging ----
    unsigned long long wlo[NBUF][4], whi[NBUF][4];
#pragma unroll
    for (int s = 0; s < NBUF - 1; ++s)
#pragma unroll
        for (int j = 0; j < 4; ++j)
            ldg16_v(wlo[s][j], whi[s][j], wbase + j * (CIN * DLEN) + s * DLEN);

    __syncthreads();   // x visible

    unsigned long long acc[4][4];         // [b][o] packed f32x2
#pragma unroll
    for (int i = 0; i < 4; ++i)
#pragma unroll
        for (int j = 0; j < 4; ++j) acc[i][j] = 0ULL;

#pragma unroll
    for (int c = 0; c < CIN; ++c) {
        // Refill FIRST: slot (c+3)&3 <- w[c+3]; consumed 3 iterations from now.
        if (c + (NBUF - 1) < CIN) {
            const int s = (c + NBUF - 1) & (NBUF - 1);
#pragma unroll
            for (int j = 0; j < 4; ++j)
                ldg16_v(wlo[s][j], whi[s][j],
                        wbase + j * (CIN * DLEN) + (c + NBUF - 1) * DLEN);
        }

        // x for this c (LDS.128 x4; 512B unique each, phase-contiguous)
        ulonglong2 xv[4];
#pragma unroll
        for (int i = 0; i < 4; ++i)
            xv[i] = *reinterpret_cast<const ulonglong2*>(xsb + i * 1024 + c * 32);

        // consume slot c&3
        const int m = c & (NBUF - 1);
#pragma unroll
        for (int i = 0; i < 4; ++i)
#pragma unroll
            for (int j = 0; j < 4; ++j) {
                acc[i][j] = ffma2(wlo[m][j], xv[i].x, acc[i][j]);   // k0,k1
                acc[i][j] = ffma2(whi[m][j], xv[i].y, acc[i][j]);   // k2,k3
            }
    }

    // ---- Epilogue ----
    const float scale = 0.17677669529663687f;   // 1/sqrt(32)
    const int p = p0 + p_l;
#pragma unroll
    for (int i = 0; i < 4; ++i)
#pragma unroll
        for (int j = 0; j < 4; ++j) {
            float2 v = *reinterpret_cast<float2*>(&acc[i][j]);
            out[(b0 + i) * (COUT * OUT_DIM) + (o0 + j) * OUT_DIM + p] =
                (v.x + v.y) * scale;
        }
}

extern "C" void kernel_launch(void* const* d_in, const int* in_sizes, int n_in,
                              void* d_out, int out_size) {
    const float* x = (const float*)d_in[0];
    const float* w = (const float*)d_in[1];
    float* out = (float*)d_out;

    cudaFuncSetAttribute(lc1d_kernel, cudaFuncAttributeMaxDynamicSharedMemorySize,
                         SMEM_BYTES);

    lc1d_kernel<<<OUT_DIM / P_TILE, NTHREADS, SMEM_BYTES>>>(x, w, out);
}